// round 2
// baseline (speedup 1.0000x reference)
#include <cuda_runtime.h>
#include <cuda_bf16.h>
#include <cstdint>

#define NB   4
#define CIN  512
#define HWD  16384
#define KCL  19
#define KC   256
#define OUTC 512

typedef unsigned long long u64;

// ---------------- packed f32x2 helpers ----------------
__device__ __forceinline__ u64 pk2(float lo, float hi) {
    u64 r;
    asm("mov.b64 %0, {%1, %2};" : "=l"(r) : "f"(lo), "f"(hi));
    return r;
}
__device__ __forceinline__ void ffma2(u64& d, u64 a, u64 b) {
    asm("fma.rn.f32x2 %0, %1, %2, %0;" : "+l"(d) : "l"(a), "l"(b));
}
__device__ __forceinline__ void fadd2(u64& d, u64 a) {
    asm("add.rn.f32x2 %0, %0, %1;" : "+l"(d) : "l"(a));
}
__device__ __forceinline__ float2 upk(u64 v) {
    float2 f;
    asm("mov.b64 {%0, %1}, %2;" : "=f"(f.x), "=f"(f.y) : "l"(v));
    return f;
}

// ---------------- scratch (device globals, zero-initialized) ----------------
__device__ float g_p[NB * KCL * HWD];
__device__ float g_proxy[NB * CIN * 20];
__device__ float g_t1[NB * KC * 20];
__device__ float g_kk[NB * KC * 20];
__device__ float g_val[NB * KC * 20];
__device__ float g_q1[(size_t)NB * KC * HWD];
__device__ float g_q2[(size_t)NB * KC * HWD];
__device__ float g_ctx[(size_t)NB * KC * HWD];
__device__ float g_up[(size_t)NB * CIN * HWD];

// ==================== 1) spatial softmax per (n,k) ====================
__global__ __launch_bounds__(256) void softmax_k(const float* __restrict__ probs) {
    const int row = blockIdx.x;
    const float* x = probs + (size_t)row * HWD;
    float* y = g_p + (size_t)row * HWD;
    __shared__ float red[8];
    const int tid = threadIdx.x, lane = tid & 31, warp = tid >> 5;

    float m = -3.4e38f;
    for (int i = tid; i < HWD; i += 256) m = fmaxf(m, x[i]);
    #pragma unroll
    for (int s = 16; s; s >>= 1) m = fmaxf(m, __shfl_xor_sync(0xffffffffu, m, s));
    if (!lane) red[warp] = m;
    __syncthreads();
    m = red[0];
    #pragma unroll
    for (int w = 1; w < 8; w++) m = fmaxf(m, red[w]);

    float sum = 0.f;
    for (int i = tid; i < HWD; i += 256) sum += __expf(x[i] - m);
    #pragma unroll
    for (int s = 16; s; s >>= 1) sum += __shfl_xor_sync(0xffffffffu, sum, s);
    __syncthreads();
    if (!lane) red[warp] = sum;
    __syncthreads();
    sum = red[0];
    #pragma unroll
    for (int w = 1; w < 8; w++) sum += red[w];
    const float inv = 1.f / sum;

    for (int i = tid; i < HWD; i += 256) y[i] = __expf(x[i] - m) * inv;
}

// ==================== 2) proxy[n,c,k] = sum_s p[n,k,s] feats[n,c,s] ====================
__global__ __launch_bounds__(256) void proxy_k(const float* __restrict__ feats) {
    const int n = blockIdx.y;
    const int warp = threadIdx.x >> 5, lane = threadIdx.x & 31;
    const int c0 = blockIdx.x * 16 + warp * 2;

    __shared__ __align__(16) float ps[128 * 22];

    u64 acc0[10], acc1[10];
    #pragma unroll
    for (int t = 0; t < 10; t++) { acc0[t] = 0ull; acc1[t] = 0ull; }

    const float* f0p = feats + ((size_t)(n * CIN + c0)) * HWD;
    const float* f1p = f0p + HWD;
    const float* pn  = g_p + (size_t)n * KCL * HWD;

    for (int sc = 0; sc < HWD; sc += 128) {
        __syncthreads();
        for (int idx = threadIdx.x; idx < KCL * 128; idx += 256) {
            int k = idx >> 7, j = idx & 127;
            ps[j * 22 + k] = pn[(size_t)k * HWD + sc + j];
        }
        if (threadIdx.x < 128) ps[threadIdx.x * 22 + 19] = 0.f;
        __syncthreads();

        #pragma unroll
        for (int jj = 0; jj < 4; jj++) {
            int j = lane + jj * 32;
            float f0 = f0p[sc + j];
            float f1 = f1p[sc + j];
            u64 f02 = pk2(f0, f0), f12 = pk2(f1, f1);
            const u64* pr = (const u64*)&ps[j * 22];
            #pragma unroll
            for (int t = 0; t < 10; t++) {
                u64 pv = pr[t];
                ffma2(acc0[t], f02, pv);
                ffma2(acc1[t], f12, pv);
            }
        }
    }
    #pragma unroll
    for (int t = 0; t < 10; t++) {
        #pragma unroll
        for (int s = 16; s; s >>= 1) {
            fadd2(acc0[t], __shfl_xor_sync(0xffffffffu, acc0[t], s));
            fadd2(acc1[t], __shfl_xor_sync(0xffffffffu, acc1[t], s));
        }
    }
    if (lane == 0) {
        float* o0 = g_proxy + (size_t)(n * CIN + c0) * 20;
        float* o1 = o0 + 20;
        #pragma unroll
        for (int t = 0; t < 10; t++) {
            float2 v0 = upk(acc0[t]);
            float2 v1 = upk(acc1[t]);
            o0[2 * t] = v0.x;
            o1[2 * t] = v1.x;
            if (2 * t + 1 < KCL) { o0[2 * t + 1] = v0.y; o1[2 * t + 1] = v1.y; }
        }
    }
}

// ==================== 3) object micro GEMM: relu((W@src+b)*s+t), 19 wide ====================
__global__ __launch_bounds__(256) void obj_gemm(
    const float* __restrict__ W, const float* __restrict__ bv,
    const float* __restrict__ sv, const float* __restrict__ tv,
    const float* __restrict__ src, float* __restrict__ dst, int Cin)
{
    extern __shared__ float src_s[];   // [Cin][22]
    const int n = blockIdx.y;
    for (int idx = threadIdx.x; idx < Cin * 20; idx += 256)
        src_s[(idx / 20) * 22 + (idx % 20)] = src[(size_t)n * Cin * 20 + idx];
    __syncthreads();

    const int g  = threadIdx.x & 15;
    const int ol = threadIdx.x >> 4;
    const int o  = blockIdx.x * 16 + ol;

    u64 acc[10];
    #pragma unroll
    for (int t = 0; t < 10; t++) acc[t] = 0ull;

    const float* wrow = W + (size_t)o * Cin;
    const int ncc = Cin >> 4;
    for (int cc = 0; cc < ncc; cc++) {
        int c = g + cc * 16;
        float w = __ldg(&wrow[c]);
        u64 w2 = pk2(w, w);
        const u64* pr = (const u64*)&src_s[c * 22];
        #pragma unroll
        for (int t = 0; t < 10; t++) ffma2(acc[t], w2, pr[t]);
    }
    #pragma unroll
    for (int t = 0; t < 10; t++) {
        #pragma unroll
        for (int s = 8; s; s >>= 1)
            fadd2(acc[t], __shfl_xor_sync(0xffffffffu, acc[t], s));
    }
    if (g == 0) {
        float bi = bv[o], sc = sv[o], ta = tv[o];
        float* dp = dst + (size_t)(n * KC + o) * 20;
        #pragma unroll
        for (int t = 0; t < 10; t++) {
            float2 v = upk(acc[t]);
            dp[2 * t] = fmaxf((v.x + bi) * sc + ta, 0.f);
            if (2 * t + 1 < KCL) dp[2 * t + 1] = fmaxf((v.y + bi) * sc + ta, 0.f);
        }
    }
}

// ==================== 4) main fp32 GEMM + fused CBR epilogue (concat-capable) ====================
__device__ __forceinline__ float4 ldB4(const float* b0, const float* b1,
                                       int Ksplit, int krow, int off) {
    const float* p = (krow < Ksplit) ? (b0 + (size_t)krow * HWD)
                                     : (b1 + (size_t)(krow - Ksplit) * HWD);
    return *(const float4*)(p + off);
}

__global__ __launch_bounds__(256, 2) void sgemm_cbr(
    const float* __restrict__ A, const float* __restrict__ B0,
    const float* __restrict__ B1, int Ksplit, int K,
    const float* __restrict__ bias, const float* __restrict__ scale,
    const float* __restrict__ tadd, float* __restrict__ Y,
    long sB0, long sB1, long sY)
{
    const int n  = blockIdx.z;
    const float* b0 = B0 + (size_t)n * sB0;
    const float* b1 = B1 + (size_t)n * sB1;
    float* y = Y + (size_t)n * sY;
    const int m0 = blockIdx.y * 128;
    const int s0 = blockIdx.x * 128;

    __shared__ __align__(16) float As[8][128];
    __shared__ __align__(16) float Bs[8][128];

    const int tid  = threadIdx.x;
    const int arow = tid >> 1;
    const int acol = (tid & 1) * 4;
    const int brow = tid >> 5;
    const int bcol = (tid & 31) * 4;
    const int tx = tid & 15;
    const int ty = tid >> 4;
    const int boff = s0 + bcol;

    u64 acc[8][4];
    #pragma unroll
    for (int i = 0; i < 8; i++)
        #pragma unroll
        for (int j = 0; j < 4; j++) acc[i][j] = 0ull;

    const int nT = K >> 3;
    float4 av = *(const float4*)&A[(size_t)(m0 + arow) * K + acol];
    float4 bv = ldB4(b0, b1, Ksplit, brow, boff);

    for (int t = 0; t < nT; t++) {
        As[acol + 0][arow] = av.x;
        As[acol + 1][arow] = av.y;
        As[acol + 2][arow] = av.z;
        As[acol + 3][arow] = av.w;
        *(float4*)&Bs[brow][bcol] = bv;
        __syncthreads();

        if (t + 1 < nT) {
            av = *(const float4*)&A[(size_t)(m0 + arow) * K + (t + 1) * 8 + acol];
            bv = ldB4(b0, b1, Ksplit, (t + 1) * 8 + brow, boff);
        }

        #pragma unroll
        for (int k = 0; k < 8; k++) {
            float4 a0 = *(const float4*)&As[k][ty * 8];
            float4 a1 = *(const float4*)&As[k][ty * 8 + 4];
            u64 ra[8];
            ra[0] = pk2(a0.x, a0.x); ra[1] = pk2(a0.y, a0.y);
            ra[2] = pk2(a0.z, a0.z); ra[3] = pk2(a0.w, a0.w);
            ra[4] = pk2(a1.x, a1.x); ra[5] = pk2(a1.y, a1.y);
            ra[6] = pk2(a1.z, a1.z); ra[7] = pk2(a1.w, a1.w);
            const u64* bp = (const u64*)&Bs[k][tx * 8];
            u64 rb0 = bp[0], rb1 = bp[1], rb2 = bp[2], rb3 = bp[3];
            #pragma unroll
            for (int i = 0; i < 8; i++) {
                ffma2(acc[i][0], ra[i], rb0);
                ffma2(acc[i][1], ra[i], rb1);
                ffma2(acc[i][2], ra[i], rb2);
                ffma2(acc[i][3], ra[i], rb3);
            }
        }
        __syncthreads();
    }

    #pragma unroll
    for (int i = 0; i < 8; i++) {
        const int o = m0 + ty * 8 + i;
        const float bi = bias[o], sc = scale[o], ta = tadd[o];
        float2 p0 = upk(acc[i][0]), p1 = upk(acc[i][1]);
        float2 p2 = upk(acc[i][2]), p3 = upk(acc[i][3]);
        float4 r0 = make_float4(fmaxf((p0.x + bi) * sc + ta, 0.f),
                                fmaxf((p0.y + bi) * sc + ta, 0.f),
                                fmaxf((p1.x + bi) * sc + ta, 0.f),
                                fmaxf((p1.y + bi) * sc + ta, 0.f));
        float4 r1 = make_float4(fmaxf((p2.x + bi) * sc + ta, 0.f),
                                fmaxf((p2.y + bi) * sc + ta, 0.f),
                                fmaxf((p3.x + bi) * sc + ta, 0.f),
                                fmaxf((p3.y + bi) * sc + ta, 0.f));
        float* yp = y + (size_t)o * HWD + s0 + tx * 8;
        *(float4*)yp = r0;
        *(float4*)(yp + 4) = r1;
    }
}

// ==================== 5) 19-way attention ====================
__global__ __launch_bounds__(256) void attn_k() {
    const int n = blockIdx.y;
    __shared__ __align__(8) float kk_s[KC * 20];
    __shared__ __align__(8) float val_s[KC * 20];
    for (int idx = threadIdx.x; idx < KC * 20; idx += 256) {
        kk_s[idx]  = g_kk[(size_t)n * KC * 20 + idx];
        val_s[idx] = g_val[(size_t)n * KC * 20 + idx];
    }
    __syncthreads();

    const int sa = blockIdx.x * 512 + threadIdx.x;
    const float* qn = g_q2 + (size_t)n * KC * HWD;

    u64 lgA[10], lgB[10];
    #pragma unroll
    for (int t = 0; t < 10; t++) { lgA[t] = 0ull; lgB[t] = 0ull; }

    #pragma unroll 2
    for (int c = 0; c < KC; c++) {
        float qa = qn[(size_t)c * HWD + sa];
        float qb = qn[(size_t)c * HWD + sa + 256];
        u64 qa2 = pk2(qa, qa), qb2 = pk2(qb, qb);
        const u64* kr = (const u64*)&kk_s[c * 20];
        #pragma unroll
        for (int t = 0; t < 10; t++) {
            u64 kv = kr[t];
            ffma2(lgA[t], qa2, kv);
            ffma2(lgB[t], qb2, kv);
        }
    }

    float la[20], lb[20];
    #pragma unroll
    for (int t = 0; t < 10; t++) {
        float2 va = upk(lgA[t]); la[2 * t] = va.x; la[2 * t + 1] = va.y;
        float2 vb = upk(lgB[t]); lb[2 * t] = vb.x; lb[2 * t + 1] = vb.y;
    }
    const float scl = 0.0625f;
    float mA = -3.4e38f, mB = -3.4e38f;
    #pragma unroll
    for (int k = 0; k < KCL; k++) {
        la[k] *= scl; lb[k] *= scl;
        mA = fmaxf(mA, la[k]); mB = fmaxf(mB, lb[k]);
    }
    float sA = 0.f, sB = 0.f;
    #pragma unroll
    for (int k = 0; k < KCL; k++) {
        la[k] = __expf(la[k] - mA); sA += la[k];
        lb[k] = __expf(lb[k] - mB); sB += lb[k];
    }
    const float ivA = 1.f / sA, ivB = 1.f / sB;
    #pragma unroll
    for (int k = 0; k < KCL; k++) { la[k] *= ivA; lb[k] *= ivB; }
    la[19] = 0.f; lb[19] = 0.f;

    u64 sA2[10], sB2[10];
    #pragma unroll
    for (int t = 0; t < 10; t++) {
        sA2[t] = pk2(la[2 * t], la[2 * t + 1]);
        sB2[t] = pk2(lb[2 * t], lb[2 * t + 1]);
    }

    float* cn = g_ctx + (size_t)n * KC * HWD;
    #pragma unroll 2
    for (int c = 0; c < KC; c++) {
        const u64* vr = (const u64*)&val_s[c * 20];
        u64 aA = 0ull, aB = 0ull;
        #pragma unroll
        for (int t = 0; t < 10; t++) {
            u64 vv = vr[t];
            ffma2(aA, sA2[t], vv);
            ffma2(aB, sB2[t], vv);
        }
        float2 va = upk(aA), vb = upk(aB);
        cn[(size_t)c * HWD + sa] = va.x + va.y;
        cn[(size_t)c * HWD + sa + 256] = vb.x + vb.y;
    }
}

// ==================== host driver ====================
extern "C" void kernel_launch(void* const* d_in, const int* in_sizes, int n_in,
                              void* d_out, int out_size) {
    const float* feats = (const float*)d_in[0];
    const float* probs = (const float*)d_in[1];
    const float* wp1 = (const float*)d_in[2];
    const float* bp1 = (const float*)d_in[3];
    const float* sp1 = (const float*)d_in[4];
    const float* tp1 = (const float*)d_in[5];
    const float* wp2 = (const float*)d_in[6];
    const float* bp2 = (const float*)d_in[7];
    const float* sp2 = (const float*)d_in[8];
    const float* tp2 = (const float*)d_in[9];
    const float* wo1 = (const float*)d_in[10];
    const float* bo1 = (const float*)d_in[11];
    const float* so1 = (const float*)d_in[12];
    const float* to1 = (const float*)d_in[13];
    const float* wo2 = (const float*)d_in[14];
    const float* bo2 = (const float*)d_in[15];
    const float* so2 = (const float*)d_in[16];
    const float* to2 = (const float*)d_in[17];
    const float* wd  = (const float*)d_in[18];
    const float* bd  = (const float*)d_in[19];
    const float* sd  = (const float*)d_in[20];
    const float* td  = (const float*)d_in[21];
    const float* wu  = (const float*)d_in[22];
    const float* bu  = (const float*)d_in[23];
    const float* su  = (const float*)d_in[24];
    const float* tu  = (const float*)d_in[25];
    const float* wf  = (const float*)d_in[26];
    const float* bf  = (const float*)d_in[27];
    const float* sf  = (const float*)d_in[28];
    const float* tf  = (const float*)d_in[29];
    float* out = (float*)d_out;

    void *pq1, *pq2, *pctx, *pup, *pproxy, *pt1, *pkk, *pval;
    cudaGetSymbolAddress(&pq1, g_q1);
    cudaGetSymbolAddress(&pq2, g_q2);
    cudaGetSymbolAddress(&pctx, g_ctx);
    cudaGetSymbolAddress(&pup, g_up);
    cudaGetSymbolAddress(&pproxy, g_proxy);
    cudaGetSymbolAddress(&pt1, g_t1);
    cudaGetSymbolAddress(&pkk, g_kk);
    cudaGetSymbolAddress(&pval, g_val);

    // 1) spatial softmax
    softmax_k<<<NB * KCL, 256>>>(probs);
    // 2) proxy gather
    proxy_k<<<dim3(32, NB), 256>>>(feats);
    // 3) object branch
    obj_gemm<<<dim3(16, NB), 256, CIN * 22 * 4>>>(wo1, bo1, so1, to1,
        (const float*)pproxy, (float*)pt1, CIN);
    obj_gemm<<<dim3(16, NB), 256, CIN * 22 * 4>>>(wd, bd, sd, td,
        (const float*)pproxy, (float*)pval, CIN);
    obj_gemm<<<dim3(16, NB), 256, KC * 22 * 4>>>(wo2, bo2, so2, to2,
        (const float*)pt1, (float*)pkk, KC);
    // 4) f_pixel stage 1: q1 = cbr(wp1 @ feats)     M=256, K=512
    sgemm_cbr<<<dim3(HWD / 128, KC / 128, NB), 256>>>(
        wp1, feats, feats, CIN, CIN, bp1, sp1, tp1,
        (float*)pq1, (long)CIN * HWD, (long)CIN * HWD, (long)KC * HWD);
    //    f_pixel stage 2: q2 = cbr(wp2 @ q1)        M=256, K=256
    sgemm_cbr<<<dim3(HWD / 128, KC / 128, NB), 256>>>(
        wp2, (const float*)pq1, (const float*)pq1, KC, KC, bp2, sp2, tp2,
        (float*)pq2, (long)KC * HWD, (long)KC * HWD, (long)KC * HWD);
    // 5) attention -> ctx
    attn_k<<<dim3(HWD / 512, NB), 256>>>();
    // 6) f_up: up = cbr(wu @ ctx)                    M=512, K=256
    sgemm_cbr<<<dim3(HWD / 128, CIN / 128, NB), 256>>>(
        wu, (const float*)pctx, (const float*)pctx, KC, KC, bu, su, tu,
        (float*)pup, (long)KC * HWD, (long)KC * HWD, (long)CIN * HWD);
    // 7) final: out = cbr(wf @ cat[up, feats])       M=512, K=1024
    sgemm_cbr<<<dim3(HWD / 128, OUTC / 128, NB), 256>>>(
        wf, (const float*)pup, feats, CIN, 2 * CIN, bf, sf, tf,
        out, (long)CIN * HWD, (long)CIN * HWD, (long)OUTC * HWD);
}

// round 3
// speedup vs baseline: 1.6903x; 1.6903x over previous
#include <cuda_runtime.h>
#include <cuda_bf16.h>
#include <cstdint>

#define NB   4
#define CIN  512
#define HWD  16384
#define KCL  19
#define KC   256
#define OUTC 512

#define BM 128
#define BN 128
#define BK 32

typedef unsigned long long u64;
typedef unsigned int u32;

// ---------------- packed f32x2 helpers (small kernels) ----------------
__device__ __forceinline__ u64 pk2(float lo, float hi) {
    u64 r; asm("mov.b64 %0, {%1, %2};" : "=l"(r) : "f"(lo), "f"(hi)); return r;
}
__device__ __forceinline__ void ffma2(u64& d, u64 a, u64 b) {
    asm("fma.rn.f32x2 %0, %1, %2, %0;" : "+l"(d) : "l"(a), "l"(b));
}
__device__ __forceinline__ void fadd2(u64& d, u64 a) {
    asm("add.rn.f32x2 %0, %0, %1;" : "+l"(d) : "l"(a));
}
__device__ __forceinline__ float2 upk(u64 v) {
    float2 f; asm("mov.b64 {%0, %1}, %2;" : "=f"(f.x), "=f"(f.y) : "l"(v)); return f;
}

// ---------------- mma helpers ----------------
__device__ __forceinline__ void ldsm4(u32* r, u32 addr) {
    asm volatile("ldmatrix.sync.aligned.m8n8.x4.shared.b16 {%0,%1,%2,%3}, [%4];\n"
        : "=r"(r[0]), "=r"(r[1]), "=r"(r[2]), "=r"(r[3]) : "r"(addr));
}
__device__ __forceinline__ void ldsm4t(u32* r, u32 addr) {
    asm volatile("ldmatrix.sync.aligned.m8n8.x4.trans.shared.b16 {%0,%1,%2,%3}, [%4];\n"
        : "=r"(r[0]), "=r"(r[1]), "=r"(r[2]), "=r"(r[3]) : "r"(addr));
}
__device__ __forceinline__ void mma16816(float* d, const u32* a, const u32* b) {
    asm volatile(
        "mma.sync.aligned.m16n8k16.row.col.f32.bf16.bf16.f32 "
        "{%0,%1,%2,%3}, {%4,%5,%6,%7}, {%8,%9}, {%0,%1,%2,%3};\n"
        : "+f"(d[0]), "+f"(d[1]), "+f"(d[2]), "+f"(d[3])
        : "r"(a[0]), "r"(a[1]), "r"(a[2]), "r"(a[3]), "r"(b[0]), "r"(b[1]));
}
__device__ __forceinline__ void split_bf16(float v, __nv_bfloat16& h, __nv_bfloat16& l) {
    h = __float2bfloat16(v);
    l = __float2bfloat16(v - __bfloat162float(h));
}
__device__ __forceinline__ void st_b162(__nv_bfloat16* p, __nv_bfloat16 a, __nv_bfloat16 b) {
    __nv_bfloat162 v; v.x = a; v.y = b; *(__nv_bfloat162*)p = v;
}

// ---------------- scratch (device globals, zero-initialized) ----------------
__device__ float g_p[NB * KCL * HWD];
__device__ float g_proxy[NB * CIN * 20];
__device__ float g_t1[NB * KC * 20];
__device__ float g_kk[NB * KC * 20];
__device__ float g_val[NB * KC * 20];
__device__ float g_q2[(size_t)NB * KC * HWD];

// triple-bf16 activations: segments [hi | hi | lo] along K
__device__ __nv_bfloat16 g_feats3[(size_t)NB * 3 * CIN * HWD];
__device__ __nv_bfloat16 g_q13[(size_t)NB * 3 * KC * HWD];
__device__ __nv_bfloat16 g_ctx3[(size_t)NB * 3 * KC * HWD];
__device__ __nv_bfloat16 g_up3[(size_t)NB * 3 * CIN * HWD];

// triple-bf16 weights: segments [hi | lo | hi] along K
__device__ __nv_bfloat16 g_wp1_3[(size_t)KC * 3 * CIN];
__device__ __nv_bfloat16 g_wp2_3[(size_t)KC * 3 * KC];
__device__ __nv_bfloat16 g_wu_3[(size_t)CIN * 3 * KC];
__device__ __nv_bfloat16 g_wf_3[(size_t)OUTC * 3 * 2 * CIN];

// ==================== spatial softmax per (n,k) ====================
__global__ __launch_bounds__(256) void softmax_k(const float* __restrict__ probs) {
    const int row = blockIdx.x;
    const float* x = probs + (size_t)row * HWD;
    float* y = g_p + (size_t)row * HWD;
    __shared__ float red[8];
    const int tid = threadIdx.x, lane = tid & 31, warp = tid >> 5;

    float m = -3.4e38f;
    for (int i = tid; i < HWD; i += 256) m = fmaxf(m, x[i]);
    #pragma unroll
    for (int s = 16; s; s >>= 1) m = fmaxf(m, __shfl_xor_sync(0xffffffffu, m, s));
    if (!lane) red[warp] = m;
    __syncthreads();
    m = red[0];
    #pragma unroll
    for (int w = 1; w < 8; w++) m = fmaxf(m, red[w]);

    float sum = 0.f;
    for (int i = tid; i < HWD; i += 256) sum += __expf(x[i] - m);
    #pragma unroll
    for (int s = 16; s; s >>= 1) sum += __shfl_xor_sync(0xffffffffu, sum, s);
    __syncthreads();
    if (!lane) red[warp] = sum;
    __syncthreads();
    sum = red[0];
    #pragma unroll
    for (int w = 1; w < 8; w++) sum += red[w];
    const float inv = 1.f / sum;

    for (int i = tid; i < HWD; i += 256) y[i] = __expf(x[i] - m) * inv;
}

// ==================== proxy[n,c,k] = sum_s p[n,k,s] feats[n,c,s] ====================
__global__ __launch_bounds__(256) void proxy_k(const float* __restrict__ feats) {
    const int n = blockIdx.y;
    const int warp = threadIdx.x >> 5, lane = threadIdx.x & 31;
    const int c0 = blockIdx.x * 16 + warp * 2;

    __shared__ __align__(16) float ps[128 * 22];

    u64 acc0[10], acc1[10];
    #pragma unroll
    for (int t = 0; t < 10; t++) { acc0[t] = 0ull; acc1[t] = 0ull; }

    const float* f0p = feats + ((size_t)(n * CIN + c0)) * HWD;
    const float* f1p = f0p + HWD;
    const float* pn  = g_p + (size_t)n * KCL * HWD;

    for (int sc = 0; sc < HWD; sc += 128) {
        __syncthreads();
        for (int idx = threadIdx.x; idx < KCL * 128; idx += 256) {
            int k = idx >> 7, j = idx & 127;
            ps[j * 22 + k] = pn[(size_t)k * HWD + sc + j];
        }
        if (threadIdx.x < 128) ps[threadIdx.x * 22 + 19] = 0.f;
        __syncthreads();

        #pragma unroll
        for (int jj = 0; jj < 4; jj++) {
            int j = lane + jj * 32;
            float f0 = f0p[sc + j];
            float f1 = f1p[sc + j];
            u64 f02 = pk2(f0, f0), f12 = pk2(f1, f1);
            const u64* pr = (const u64*)&ps[j * 22];
            #pragma unroll
            for (int t = 0; t < 10; t++) {
                u64 pv = pr[t];
                ffma2(acc0[t], f02, pv);
                ffma2(acc1[t], f12, pv);
            }
        }
    }
    #pragma unroll
    for (int t = 0; t < 10; t++) {
        #pragma unroll
        for (int s = 16; s; s >>= 1) {
            fadd2(acc0[t], __shfl_xor_sync(0xffffffffu, acc0[t], s));
            fadd2(acc1[t], __shfl_xor_sync(0xffffffffu, acc1[t], s));
        }
    }
    if (lane == 0) {
        float* o0 = g_proxy + (size_t)(n * CIN + c0) * 20;
        float* o1 = o0 + 20;
        #pragma unroll
        for (int t = 0; t < 10; t++) {
            float2 v0 = upk(acc0[t]);
            float2 v1 = upk(acc1[t]);
            o0[2 * t] = v0.x;
            o1[2 * t] = v1.x;
            if (2 * t + 1 < KCL) { o0[2 * t + 1] = v0.y; o1[2 * t + 1] = v1.y; }
        }
    }
}

// ==================== object micro GEMM ====================
__global__ __launch_bounds__(256) void obj_gemm(
    const float* __restrict__ W, const float* __restrict__ bv,
    const float* __restrict__ sv, const float* __restrict__ tv,
    const float* __restrict__ src, float* __restrict__ dst, int Cin)
{
    extern __shared__ float src_s[];
    const int n = blockIdx.y;
    for (int idx = threadIdx.x; idx < Cin * 20; idx += 256)
        src_s[(idx / 20) * 22 + (idx % 20)] = src[(size_t)n * Cin * 20 + idx];
    __syncthreads();

    const int g  = threadIdx.x & 15;
    const int ol = threadIdx.x >> 4;
    const int o  = blockIdx.x * 16 + ol;

    u64 acc[10];
    #pragma unroll
    for (int t = 0; t < 10; t++) acc[t] = 0ull;

    const float* wrow = W + (size_t)o * Cin;
    const int ncc = Cin >> 4;
    for (int cc = 0; cc < ncc; cc++) {
        int c = g + cc * 16;
        float w = __ldg(&wrow[c]);
        u64 w2 = pk2(w, w);
        const u64* pr = (const u64*)&src_s[c * 22];
        #pragma unroll
        for (int t = 0; t < 10; t++) ffma2(acc[t], w2, pr[t]);
    }
    #pragma unroll
    for (int t = 0; t < 10; t++) {
        #pragma unroll
        for (int s = 8; s; s >>= 1)
            fadd2(acc[t], __shfl_xor_sync(0xffffffffu, acc[t], s));
    }
    if (g == 0) {
        float bi = bv[o], sc = sv[o], ta = tv[o];
        float* dp = dst + (size_t)(n * KC + o) * 20;
        #pragma unroll
        for (int t = 0; t < 10; t++) {
            float2 v = upk(acc[t]);
            dp[2 * t] = fmaxf((v.x + bi) * sc + ta, 0.f);
            if (2 * t + 1 < KCL) dp[2 * t + 1] = fmaxf((v.y + bi) * sc + ta, 0.f);
        }
    }
}

// ==================== converters ====================
// feats -> triple bf16 [n][3*CIN][HWD], segments [hi|hi|lo]
__global__ __launch_bounds__(256) void conv_feats(const float* __restrict__ X) {
    const size_t TOT4 = (size_t)NB * CIN * HWD / 4;
    size_t i4 = (size_t)blockIdx.x * 256 + threadIdx.x;
    if (i4 >= TOT4) return;
    size_t row = i4 >> 12;                 // / (HWD/4)
    int s = (int)(i4 & 4095) * 4;
    int n = (int)(row >> 9), c = (int)(row & 511);
    float4 v = *(const float4*)(X + row * HWD + s);
    __nv_bfloat16 h0, h1, h2, h3, l0, l1, l2, l3;
    split_bf16(v.x, h0, l0); split_bf16(v.y, h1, l1);
    split_bf16(v.z, h2, l2); split_bf16(v.w, h3, l3);
    __nv_bfloat16* base = g_feats3 + ((size_t)n * 3 * CIN + c) * HWD + s;
    st_b162(base, h0, h1); st_b162(base + 2, h2, h3);
    __nv_bfloat16* b2 = base + (size_t)CIN * HWD;
    st_b162(b2, h0, h1); st_b162(b2 + 2, h2, h3);
    __nv_bfloat16* b3 = base + (size_t)2 * CIN * HWD;
    st_b162(b3, l0, l1); st_b162(b3 + 2, l2, l3);
}

// W[M][K] -> triple bf16 [M][3K], segments [hi|lo|hi]
__global__ __launch_bounds__(256) void conv_w(const float* __restrict__ W,
                                              __nv_bfloat16* __restrict__ A3,
                                              int M, int K) {
    int i = blockIdx.x * 256 + threadIdx.x;
    if (i >= M * K) return;
    int m = i / K, k = i - m * K;
    __nv_bfloat16 h, l;
    split_bf16(W[i], h, l);
    __nv_bfloat16* r = A3 + (size_t)m * 3 * K;
    r[k] = h; r[K + k] = l; r[2 * K + k] = h;
}

// ==================== bf16 MMA GEMM + fused CBR epilogue ====================
// Y[o,s] = relu((sum_k3 A3[o,k3] * B3[k3,s] + bias[o]) * scale[o] + t[o])
// B rows: r -> seg=r>>kshift, kk=r&(Kseg-1); kk<Ksplit -> B0 else B1.
__global__ __launch_bounds__(256, 2) void gemm_mma_cbr(
    const __nv_bfloat16* __restrict__ A,
    const __nv_bfloat16* __restrict__ B0, const __nv_bfloat16* __restrict__ B1,
    int Ksplit, int kshift, int K3,
    const float* __restrict__ bias, const float* __restrict__ scale,
    const float* __restrict__ tadd,
    float* __restrict__ Yf, long sYf,
    __nv_bfloat16* __restrict__ Y3, long sY3, int Mout,
    long sB0, long sB1)
{
    const int n  = blockIdx.z;
    const int m0 = blockIdx.y * BM;
    const int s0 = blockIdx.x * BN;
    const int Kseg = 1 << kshift;
    const int kw2  = Kseg - Ksplit;

    const int tid = threadIdx.x;
    const int lane = tid & 31, warp = tid >> 5;
    const int wm = warp >> 2, wn = warp & 3;   // 2 x 4 warps, warp tile 64x32

    __shared__ __align__(16) __nv_bfloat16 As[2][BM][BK + 8];
    __shared__ __align__(16) __nv_bfloat16 Bs[2][BK][BN + 8];

    const __nv_bfloat16* b0 = B0 + (size_t)n * sB0;
    const __nv_bfloat16* b1 = B1 + (size_t)n * sB1;

    // loader geometry
    const int aRow = tid >> 1;                 // 0..127
    const int aCol = (tid & 1) * 16;           // 0 / 16
    const int bRow = tid >> 3;                 // 0..31
    const int bCol = (tid & 7) * 16;           // 0..112

    const __nv_bfloat16* aG = A + (size_t)(m0 + aRow) * K3 + aCol;

    float acc[4][4][4];
    #pragma unroll
    for (int mi = 0; mi < 4; mi++)
        #pragma unroll
        for (int ni = 0; ni < 4; ni++)
            #pragma unroll
            for (int q = 0; q < 4; q++) acc[mi][ni][q] = 0.f;

    u32 asBase = (u32)__cvta_generic_to_shared(&As[0][0][0]);
    u32 bsBase = (u32)__cvta_generic_to_shared(&Bs[0][0][0]);
    const u32 aBuf = BM * (BK + 8) * 2;
    const u32 bBuf = BK * (BN + 8) * 2;
    const u32 aAddr0 = asBase + ((wm * 64 + (lane & 15)) * (BK + 8) + ((lane >> 4) << 3)) * 2;
    const u32 bAddr0 = bsBase + ((lane & 15) * (BN + 8) + wn * 32 + ((lane >> 4) << 3)) * 2;
    const u32 A_MI = 16 * (BK + 8) * 2;
    const u32 B_KS = 16 * (BN + 8) * 2;

    const int nT = K3 / BK;
    uint4 pa0, pa1, pb0, pb1;

    // prefetch tile 0
    {
        pa0 = *(const uint4*)aG;
        pa1 = *(const uint4*)(aG + 8);
        int r = bRow;
        int seg = r >> kshift, kk = r & (Kseg - 1);
        const __nv_bfloat16* rp = (kk < Ksplit)
            ? b0 + (size_t)(seg * Ksplit + kk) * HWD
            : b1 + (size_t)(seg * kw2 + kk - Ksplit) * HWD;
        rp += s0 + bCol;
        pb0 = *(const uint4*)rp;
        pb1 = *(const uint4*)(rp + 8);
    }

    for (int t = 0; t < nT; t++) {
        const int buf = t & 1;
        *(uint4*)&As[buf][aRow][aCol]     = pa0;
        *(uint4*)&As[buf][aRow][aCol + 8] = pa1;
        *(uint4*)&Bs[buf][bRow][bCol]     = pb0;
        *(uint4*)&Bs[buf][bRow][bCol + 8] = pb1;
        __syncthreads();

        if (t + 1 < nT) {
            const __nv_bfloat16* ag = aG + (size_t)(t + 1) * BK;
            pa0 = *(const uint4*)ag;
            pa1 = *(const uint4*)(ag + 8);
            int r = (t + 1) * BK + bRow;
            int seg = r >> kshift, kk = r & (Kseg - 1);
            const __nv_bfloat16* rp = (kk < Ksplit)
                ? b0 + (size_t)(seg * Ksplit + kk) * HWD
                : b1 + (size_t)(seg * kw2 + kk - Ksplit) * HWD;
            rp += s0 + bCol;
            pb0 = *(const uint4*)rp;
            pb1 = *(const uint4*)(rp + 8);
        }

        const u32 aA = aAddr0 + buf * aBuf;
        const u32 bA = bAddr0 + buf * bBuf;
        #pragma unroll
        for (int ks = 0; ks < 2; ks++) {
            u32 ra[4][4];
            #pragma unroll
            for (int mi = 0; mi < 4; mi++) ldsm4(ra[mi], aA + mi * A_MI + ks * 32);
            u32 rb0a[4], rb1a[4];
            ldsm4t(rb0a, bA + ks * B_KS);
            ldsm4t(rb1a, bA + ks * B_KS + 32);
            #pragma unroll
            for (int mi = 0; mi < 4; mi++) {
                mma16816(acc[mi][0], ra[mi], &rb0a[0]);
                mma16816(acc[mi][1], ra[mi], &rb0a[2]);
                mma16816(acc[mi][2], ra[mi], &rb1a[0]);
                mma16816(acc[mi][3], ra[mi], &rb1a[2]);
            }
        }
        __syncthreads();
    }

    // epilogue
    const int orow = lane >> 2;
    const int scol = (lane & 3) * 2;
    if (Yf) {
        float* y = Yf + (size_t)n * sYf;
        #pragma unroll
        for (int mi = 0; mi < 4; mi++) {
            const int oA = m0 + wm * 64 + mi * 16 + orow;
            const int oB = oA + 8;
            const float biA = bias[oA], scA = scale[oA], taA = tadd[oA];
            const float biB = bias[oB], scB = scale[oB], taB = tadd[oB];
            #pragma unroll
            for (int ni = 0; ni < 4; ni++) {
                const int s = s0 + wn * 32 + ni * 8 + scol;
                float2 r0 = make_float2(
                    fmaxf((acc[mi][ni][0] + biA) * scA + taA, 0.f),
                    fmaxf((acc[mi][ni][1] + biA) * scA + taA, 0.f));
                float2 r1 = make_float2(
                    fmaxf((acc[mi][ni][2] + biB) * scB + taB, 0.f),
                    fmaxf((acc[mi][ni][3] + biB) * scB + taB, 0.f));
                *(float2*)(y + (size_t)oA * HWD + s) = r0;
                *(float2*)(y + (size_t)oB * HWD + s) = r1;
            }
        }
    } else {
        __nv_bfloat16* y3 = Y3 + (size_t)n * sY3;
        const size_t segStride = (size_t)Mout * HWD;
        #pragma unroll
        for (int mi = 0; mi < 4; mi++) {
            const int oA = m0 + wm * 64 + mi * 16 + orow;
            const int oB = oA + 8;
            const float biA = bias[oA], scA = scale[oA], taA = tadd[oA];
            const float biB = bias[oB], scB = scale[oB], taB = tadd[oB];
            #pragma unroll
            for (int ni = 0; ni < 4; ni++) {
                const int s = s0 + wn * 32 + ni * 8 + scol;
                float vA0 = fmaxf((acc[mi][ni][0] + biA) * scA + taA, 0.f);
                float vA1 = fmaxf((acc[mi][ni][1] + biA) * scA + taA, 0.f);
                float vB0 = fmaxf((acc[mi][ni][2] + biB) * scB + taB, 0.f);
                float vB1 = fmaxf((acc[mi][ni][3] + biB) * scB + taB, 0.f);
                __nv_bfloat16 hA0, lA0, hA1, lA1, hB0, lB0, hB1, lB1;
                split_bf16(vA0, hA0, lA0); split_bf16(vA1, hA1, lA1);
                split_bf16(vB0, hB0, lB0); split_bf16(vB1, hB1, lB1);
                __nv_bfloat16* pA = y3 + (size_t)oA * HWD + s;
                __nv_bfloat16* pB = y3 + (size_t)oB * HWD + s;
                st_b162(pA, hA0, hA1);
                st_b162(pA + segStride, hA0, hA1);
                st_b162(pA + 2 * segStride, lA0, lA1);
                st_b162(pB, hB0, hB1);
                st_b162(pB + segStride, hB0, hB1);
                st_b162(pB + 2 * segStride, lB0, lB1);
            }
        }
    }
}

// ==================== 19-way attention (reads q2 fp32, writes ctx triple) ====================
__global__ __launch_bounds__(256) void attn_k() {
    const int n = blockIdx.y;
    __shared__ __align__(8) float kk_s[KC * 20];
    __shared__ __align__(8) float val_s[KC * 20];
    for (int idx = threadIdx.x; idx < KC * 20; idx += 256) {
        kk_s[idx]  = g_kk[(size_t)n * KC * 20 + idx];
        val_s[idx] = g_val[(size_t)n * KC * 20 + idx];
    }
    __syncthreads();

    const int sa = blockIdx.x * 512 + threadIdx.x;
    const float* qn = g_q2 + (size_t)n * KC * HWD;

    u64 lgA[10], lgB[10];
    #pragma unroll
    for (int t = 0; t < 10; t++) { lgA[t] = 0ull; lgB[t] = 0ull; }

    #pragma unroll 2
    for (int c = 0; c < KC; c++) {
        float qa = qn[(size_t)c * HWD + sa];
        float qb = qn[(size_t)c * HWD + sa + 256];
        u64 qa2 = pk2(qa, qa), qb2 = pk2(qb, qb);
        const u64* kr = (const u64*)&kk_s[c * 20];
        #pragma unroll
        for (int t = 0; t < 10; t++) {
            u64 kv = kr[t];
            ffma2(lgA[t], qa2, kv);
            ffma2(lgB[t], qb2, kv);
        }
    }

    float la[20], lb[20];
    #pragma unroll
    for (int t = 0; t < 10; t++) {
        float2 va = upk(lgA[t]); la[2 * t] = va.x; la[2 * t + 1] = va.y;
        float2 vb = upk(lgB[t]); lb[2 * t] = vb.x; lb[2 * t + 1] = vb.y;
    }
    const float scl = 0.0625f;
    float mA = -3.4e38f, mB = -3.4e38f;
    #pragma unroll
    for (int k = 0; k < KCL; k++) {
        la[k] *= scl; lb[k] *= scl;
        mA = fmaxf(mA, la[k]); mB = fmaxf(mB, lb[k]);
    }
    float sA = 0.f, sB = 0.f;
    #pragma unroll
    for (int k = 0; k < KCL; k++) {
        la[k] = __expf(la[k] - mA); sA += la[k];
        lb[k] = __expf(lb[k] - mB); sB += lb[k];
    }
    const float ivA = 1.f / sA, ivB = 1.f / sB;
    #pragma unroll
    for (int k = 0; k < KCL; k++) { la[k] *= ivA; lb[k] *= ivB; }
    la[19] = 0.f; lb[19] = 0.f;

    u64 sA2[10], sB2[10];
    #pragma unroll
    for (int t = 0; t < 10; t++) {
        sA2[t] = pk2(la[2 * t], la[2 * t + 1]);
        sB2[t] = pk2(lb[2 * t], lb[2 * t + 1]);
    }

    __nv_bfloat16* cn3 = g_ctx3 + (size_t)n * 3 * KC * HWD;
    const size_t segStride = (size_t)KC * HWD;
    #pragma unroll 2
    for (int c = 0; c < KC; c++) {
        const u64* vr = (const u64*)&val_s[c * 20];
        u64 aA = 0ull, aB = 0ull;
        #pragma unroll
        for (int t = 0; t < 10; t++) {
            u64 vv = vr[t];
            ffma2(aA, sA2[t], vv);
            ffma2(aB, sB2[t], vv);
        }
        float2 va = upk(aA), vb = upk(aB);
        float vx = va.x + va.y;
        float vy = vb.x + vb.y;
        __nv_bfloat16 hx, lx, hy, ly;
        split_bf16(vx, hx, lx);
        split_bf16(vy, hy, ly);
        __nv_bfloat16* p = cn3 + (size_t)c * HWD + sa;
        p[0] = hx; p[256] = hy;
        p[segStride] = hx; p[segStride + 256] = hy;
        p[2 * segStride] = lx; p[2 * segStride + 256] = ly;
    }
}

// ==================== host driver ====================
extern "C" void kernel_launch(void* const* d_in, const int* in_sizes, int n_in,
                              void* d_out, int out_size) {
    const float* feats = (const float*)d_in[0];
    const float* probs = (const float*)d_in[1];
    const float* wp1 = (const float*)d_in[2];
    const float* bp1 = (const float*)d_in[3];
    const float* sp1 = (const float*)d_in[4];
    const float* tp1 = (const float*)d_in[5];
    const float* wp2 = (const float*)d_in[6];
    const float* bp2 = (const float*)d_in[7];
    const float* sp2 = (const float*)d_in[8];
    const float* tp2 = (const float*)d_in[9];
    const float* wo1 = (const float*)d_in[10];
    const float* bo1 = (const float*)d_in[11];
    const float* so1 = (const float*)d_in[12];
    const float* to1 = (const float*)d_in[13];
    const float* wo2 = (const float*)d_in[14];
    const float* bo2 = (const float*)d_in[15];
    const float* so2 = (const float*)d_in[16];
    const float* to2 = (const float*)d_in[17];
    const float* wd  = (const float*)d_in[18];
    const float* bd  = (const float*)d_in[19];
    const float* sd  = (const float*)d_in[20];
    const float* td  = (const float*)d_in[21];
    const float* wu  = (const float*)d_in[22];
    const float* bu  = (const float*)d_in[23];
    const float* su  = (const float*)d_in[24];
    const float* tu  = (const float*)d_in[25];
    const float* wf  = (const float*)d_in[26];
    const float* bf  = (const float*)d_in[27];
    const float* sf  = (const float*)d_in[28];
    const float* tf  = (const float*)d_in[29];
    float* out = (float*)d_out;

    void *pproxy, *pt1, *pkk, *pval, *pq2;
    void *pfeats3, *pq13, *pctx3, *pup3, *pw1, *pw2, *pwu, *pwf;
    cudaGetSymbolAddress(&pproxy, g_proxy);
    cudaGetSymbolAddress(&pt1, g_t1);
    cudaGetSymbolAddress(&pkk, g_kk);
    cudaGetSymbolAddress(&pval, g_val);
    cudaGetSymbolAddress(&pq2, g_q2);
    cudaGetSymbolAddress(&pfeats3, g_feats3);
    cudaGetSymbolAddress(&pq13, g_q13);
    cudaGetSymbolAddress(&pctx3, g_ctx3);
    cudaGetSymbolAddress(&pup3, g_up3);
    cudaGetSymbolAddress(&pw1, g_wp1_3);
    cudaGetSymbolAddress(&pw2, g_wp2_3);
    cudaGetSymbolAddress(&pwu, g_wu_3);
    cudaGetSymbolAddress(&pwf, g_wf_3);

    // converters
    conv_feats<<<(NB * CIN * HWD / 4 + 255) / 256, 256>>>(feats);
    conv_w<<<(KC * CIN + 255) / 256, 256>>>(wp1, (__nv_bfloat16*)pw1, KC, CIN);
    conv_w<<<(KC * KC + 255) / 256, 256>>>(wp2, (__nv_bfloat16*)pw2, KC, KC);
    conv_w<<<(CIN * KC + 255) / 256, 256>>>(wu, (__nv_bfloat16*)pwu, CIN, KC);
    conv_w<<<(OUTC * 2 * CIN + 255) / 256, 256>>>(wf, (__nv_bfloat16*)pwf, OUTC, 2 * CIN);

    // softmax + proxy + object branch
    softmax_k<<<NB * KCL, 256>>>(probs);
    proxy_k<<<dim3(32, NB), 256>>>(feats);
    obj_gemm<<<dim3(16, NB), 256, CIN * 22 * 4>>>(wo1, bo1, so1, to1,
        (const float*)pproxy, (float*)pt1, CIN);
    obj_gemm<<<dim3(16, NB), 256, CIN * 22 * 4>>>(wd, bd, sd, td,
        (const float*)pproxy, (float*)pval, CIN);
    obj_gemm<<<dim3(16, NB), 256, KC * 22 * 4>>>(wo2, bo2, so2, to2,
        (const float*)pt1, (float*)pkk, KC);

    // f_pixel stage 1: q1(triple) = cbr(wp1 @ feats)     M=256, Kseg=512
    gemm_mma_cbr<<<dim3(HWD / BN, KC / BM, NB), 256>>>(
        (const __nv_bfloat16*)pw1,
        (const __nv_bfloat16*)pfeats3, (const __nv_bfloat16*)pfeats3,
        CIN, 9, 3 * CIN, bp1, sp1, tp1,
        nullptr, 0,
        (__nv_bfloat16*)pq13, 3L * KC * HWD, KC,
        3L * CIN * HWD, 3L * CIN * HWD);

    // f_pixel stage 2: q2(fp32) = cbr(wp2 @ q1)          M=256, Kseg=256
    gemm_mma_cbr<<<dim3(HWD / BN, KC / BM, NB), 256>>>(
        (const __nv_bfloat16*)pw2,
        (const __nv_bfloat16*)pq13, (const __nv_bfloat16*)pq13,
        KC, 8, 3 * KC, bp2, sp2, tp2,
        (float*)pq2, (long)KC * HWD,
        nullptr, 0, 0,
        3L * KC * HWD, 3L * KC * HWD);

    // attention -> ctx (triple)
    attn_k<<<dim3(HWD / 512, NB), 256>>>();

    // f_up: up(triple) = cbr(wu @ ctx)                   M=512, Kseg=256
    gemm_mma_cbr<<<dim3(HWD / BN, CIN / BM, NB), 256>>>(
        (const __nv_bfloat16*)pwu,
        (const __nv_bfloat16*)pctx3, (const __nv_bfloat16*)pctx3,
        KC, 8, 3 * KC, bu, su, tu,
        nullptr, 0,
        (__nv_bfloat16*)pup3, 3L * CIN * HWD, CIN,
        3L * KC * HWD, 3L * KC * HWD);

    // final: out(fp32) = cbr(wf @ cat[up, feats])        M=512, Kseg=1024, Ksplit=512
    gemm_mma_cbr<<<dim3(HWD / BN, OUTC / BM, NB), 256>>>(
        (const __nv_bfloat16*)pwf,
        (const __nv_bfloat16*)pup3, (const __nv_bfloat16*)pfeats3,
        CIN, 10, 3 * 2 * CIN, bf, sf, tf,
        out, (long)OUTC * HWD,
        nullptr, 0, 0,
        3L * CIN * HWD, 3L * CIN * HWD);
}

// round 4
// speedup vs baseline: 1.9069x; 1.1281x over previous
#include <cuda_runtime.h>
#include <cuda_bf16.h>
#include <cstdint>

#define NB   4
#define CIN  512
#define HWD  16384
#define KCL  19
#define KC   256
#define OUTC 512

#define BM 128
#define BN 128
#define BK 32

typedef unsigned long long u64;
typedef unsigned int u32;

// ---------------- packed f32x2 helpers (small kernels) ----------------
__device__ __forceinline__ u64 pk2(float lo, float hi) {
    u64 r; asm("mov.b64 %0, {%1, %2};" : "=l"(r) : "f"(lo), "f"(hi)); return r;
}
__device__ __forceinline__ void ffma2(u64& d, u64 a, u64 b) {
    asm("fma.rn.f32x2 %0, %1, %2, %0;" : "+l"(d) : "l"(a), "l"(b));
}
__device__ __forceinline__ void fadd2(u64& d, u64 a) {
    asm("add.rn.f32x2 %0, %0, %1;" : "+l"(d) : "l"(a));
}
__device__ __forceinline__ float2 upk(u64 v) {
    float2 f; asm("mov.b64 {%0, %1}, %2;" : "=f"(f.x), "=f"(f.y) : "l"(v)); return f;
}

// ---------------- mma helpers ----------------
__device__ __forceinline__ void ldsm4(u32* r, u32 addr) {
    asm volatile("ldmatrix.sync.aligned.m8n8.x4.shared.b16 {%0,%1,%2,%3}, [%4];\n"
        : "=r"(r[0]), "=r"(r[1]), "=r"(r[2]), "=r"(r[3]) : "r"(addr));
}
__device__ __forceinline__ void ldsm4t(u32* r, u32 addr) {
    asm volatile("ldmatrix.sync.aligned.m8n8.x4.trans.shared.b16 {%0,%1,%2,%3}, [%4];\n"
        : "=r"(r[0]), "=r"(r[1]), "=r"(r[2]), "=r"(r[3]) : "r"(addr));
}
__device__ __forceinline__ void mma16816(float* d, const u32* a, const u32* b) {
    asm volatile(
        "mma.sync.aligned.m16n8k16.row.col.f32.bf16.bf16.f32 "
        "{%0,%1,%2,%3}, {%4,%5,%6,%7}, {%8,%9}, {%0,%1,%2,%3};\n"
        : "+f"(d[0]), "+f"(d[1]), "+f"(d[2]), "+f"(d[3])
        : "r"(a[0]), "r"(a[1]), "r"(a[2]), "r"(a[3]), "r"(b[0]), "r"(b[1]));
}
__device__ __forceinline__ void split_bf16(float v, __nv_bfloat16& h, __nv_bfloat16& l) {
    h = __float2bfloat16(v);
    l = __float2bfloat16(v - __bfloat162float(h));
}

union U16B {
    __nv_bfloat16 v[16];
    uint4 q[2];
};

// ---------------- scratch (device globals, zero-initialized) ----------------
__device__ float g_p[NB * KCL * HWD];
__device__ float g_proxy[NB * CIN * 20];
__device__ float g_t1[NB * KC * 20];
__device__ float g_kk[NB * KC * 20];
__device__ float g_val[NB * KC * 20];
__device__ float g_q1[(size_t)NB * KC * HWD];
__device__ float g_q2[(size_t)NB * KC * HWD];
__device__ float g_ctx[(size_t)NB * KC * HWD];
__device__ float g_up[(size_t)NB * CIN * HWD];

// split weights: [hi M*K][lo M*K]
__device__ __nv_bfloat16 g_wp1_2[2 * (size_t)KC * CIN];
__device__ __nv_bfloat16 g_wp2_2[2 * (size_t)KC * KC];
__device__ __nv_bfloat16 g_wu_2[2 * (size_t)CIN * KC];
__device__ __nv_bfloat16 g_wf_2[2 * (size_t)OUTC * 2 * CIN];

// ==================== spatial softmax per (n,k) ====================
__global__ __launch_bounds__(256) void softmax_k(const float* __restrict__ probs) {
    const int row = blockIdx.x;
    const float* x = probs + (size_t)row * HWD;
    float* y = g_p + (size_t)row * HWD;
    __shared__ float red[8];
    const int tid = threadIdx.x, lane = tid & 31, warp = tid >> 5;

    float m = -3.4e38f;
    for (int i = tid; i < HWD; i += 256) m = fmaxf(m, x[i]);
    #pragma unroll
    for (int s = 16; s; s >>= 1) m = fmaxf(m, __shfl_xor_sync(0xffffffffu, m, s));
    if (!lane) red[warp] = m;
    __syncthreads();
    m = red[0];
    #pragma unroll
    for (int w = 1; w < 8; w++) m = fmaxf(m, red[w]);

    float sum = 0.f;
    for (int i = tid; i < HWD; i += 256) sum += __expf(x[i] - m);
    #pragma unroll
    for (int s = 16; s; s >>= 1) sum += __shfl_xor_sync(0xffffffffu, sum, s);
    __syncthreads();
    if (!lane) red[warp] = sum;
    __syncthreads();
    sum = red[0];
    #pragma unroll
    for (int w = 1; w < 8; w++) sum += red[w];
    const float inv = 1.f / sum;

    for (int i = tid; i < HWD; i += 256) y[i] = __expf(x[i] - m) * inv;
}

// ==================== proxy[n,c,k] = sum_s p[n,k,s] feats[n,c,s] ====================
__global__ __launch_bounds__(256) void proxy_k(const float* __restrict__ feats) {
    const int n = blockIdx.y;
    const int warp = threadIdx.x >> 5, lane = threadIdx.x & 31;
    const int c0 = blockIdx.x * 16 + warp * 2;

    __shared__ __align__(16) float ps[128 * 22];

    u64 acc0[10], acc1[10];
    #pragma unroll
    for (int t = 0; t < 10; t++) { acc0[t] = 0ull; acc1[t] = 0ull; }

    const float* f0p = feats + ((size_t)(n * CIN + c0)) * HWD;
    const float* f1p = f0p + HWD;
    const float* pn  = g_p + (size_t)n * KCL * HWD;

    for (int sc = 0; sc < HWD; sc += 128) {
        __syncthreads();
        for (int idx = threadIdx.x; idx < KCL * 128; idx += 256) {
            int k = idx >> 7, j = idx & 127;
            ps[j * 22 + k] = pn[(size_t)k * HWD + sc + j];
        }
        if (threadIdx.x < 128) ps[threadIdx.x * 22 + 19] = 0.f;
        __syncthreads();

        #pragma unroll
        for (int jj = 0; jj < 4; jj++) {
            int j = lane + jj * 32;
            float f0 = f0p[sc + j];
            float f1 = f1p[sc + j];
            u64 f02 = pk2(f0, f0), f12 = pk2(f1, f1);
            const u64* pr = (const u64*)&ps[j * 22];
            #pragma unroll
            for (int t = 0; t < 10; t++) {
                u64 pv = pr[t];
                ffma2(acc0[t], f02, pv);
                ffma2(acc1[t], f12, pv);
            }
        }
    }
    #pragma unroll
    for (int t = 0; t < 10; t++) {
        #pragma unroll
        for (int s = 16; s; s >>= 1) {
            fadd2(acc0[t], __shfl_xor_sync(0xffffffffu, acc0[t], s));
            fadd2(acc1[t], __shfl_xor_sync(0xffffffffu, acc1[t], s));
        }
    }
    if (lane == 0) {
        float* o0 = g_proxy + (size_t)(n * CIN + c0) * 20;
        float* o1 = o0 + 20;
        #pragma unroll
        for (int t = 0; t < 10; t++) {
            float2 v0 = upk(acc0[t]);
            float2 v1 = upk(acc1[t]);
            o0[2 * t] = v0.x;
            o1[2 * t] = v1.x;
            if (2 * t + 1 < KCL) { o0[2 * t + 1] = v0.y; o1[2 * t + 1] = v1.y; }
        }
    }
}

// ==================== object micro GEMM ====================
__global__ __launch_bounds__(256) void obj_gemm(
    const float* __restrict__ W, const float* __restrict__ bv,
    const float* __restrict__ sv, const float* __restrict__ tv,
    const float* __restrict__ src, float* __restrict__ dst, int Cin)
{
    extern __shared__ float src_s[];
    const int n = blockIdx.y;
    for (int idx = threadIdx.x; idx < Cin * 20; idx += 256)
        src_s[(idx / 20) * 22 + (idx % 20)] = src[(size_t)n * Cin * 20 + idx];
    __syncthreads();

    const int g  = threadIdx.x & 15;
    const int ol = threadIdx.x >> 4;
    const int o  = blockIdx.x * 16 + ol;

    u64 acc[10];
    #pragma unroll
    for (int t = 0; t < 10; t++) acc[t] = 0ull;

    const float* wrow = W + (size_t)o * Cin;
    const int ncc = Cin >> 4;
    for (int cc = 0; cc < ncc; cc++) {
        int c = g + cc * 16;
        float w = __ldg(&wrow[c]);
        u64 w2 = pk2(w, w);
        const u64* pr = (const u64*)&src_s[c * 22];
        #pragma unroll
        for (int t = 0; t < 10; t++) ffma2(acc[t], w2, pr[t]);
    }
    #pragma unroll
    for (int t = 0; t < 10; t++) {
        #pragma unroll
        for (int s = 8; s; s >>= 1)
            fadd2(acc[t], __shfl_xor_sync(0xffffffffu, acc[t], s));
    }
    if (g == 0) {
        float bi = bv[o], sc = sv[o], ta = tv[o];
        float* dp = dst + (size_t)(n * KC + o) * 20;
        #pragma unroll
        for (int t = 0; t < 10; t++) {
            float2 v = upk(acc[t]);
            dp[2 * t] = fmaxf((v.x + bi) * sc + ta, 0.f);
            if (2 * t + 1 < KCL) dp[2 * t + 1] = fmaxf((v.y + bi) * sc + ta, 0.f);
        }
    }
}

// ==================== weight splitter: W[M][K] -> [hi M*K][lo M*K] bf16 ====================
__global__ __launch_bounds__(256) void conv_w(const float* __restrict__ W,
                                              __nv_bfloat16* __restrict__ A2,
                                              int MK) {
    int i = blockIdx.x * 256 + threadIdx.x;
    if (i >= MK) return;
    __nv_bfloat16 h, l;
    split_bf16(W[i], h, l);
    A2[i] = h;
    A2[MK + i] = l;
}

// ==================== compensated-bf16 MMA GEMM + fused CBR epilogue ====================
// Y[o,s] = relu((sum_k A[o,k]*B[k,s] + bias[o]) * scale[o] + t[o])
// A2 = [Ah (M*K) | Al (M*K)] bf16. B rows fp32: r<Ksplit -> B0 else B1.
// acc = Ah*Bh + Al*Bh + Ah*Bl   (drops Al*Bl ~ 2^-18)
__global__ __launch_bounds__(256) void gemm_mma_cbr(
    const __nv_bfloat16* __restrict__ A2, int K, int nMB,
    const float* __restrict__ B0, const float* __restrict__ B1, int Ksplit,
    const float* __restrict__ bias, const float* __restrict__ scale,
    const float* __restrict__ tadd,
    float* __restrict__ Y, long sB0, long sB1, long sY)
{
    const int n = blockIdx.z;
    const int mIdx = blockIdx.x % nMB;
    const int sIdx = blockIdx.x / nMB;
    const int m0 = mIdx * BM;
    const int s0 = sIdx * BN;

    const int tid = threadIdx.x;
    const int lane = tid & 31, warp = tid >> 5;
    const int wm = warp >> 2, wn = warp & 3;       // 2 x 4 warps, warp tile 64x32

    extern __shared__ __align__(16) char smem[];
    __nv_bfloat16* AsH = (__nv_bfloat16*)smem;     // [2][128][40]
    __nv_bfloat16* AsL = AsH + 2 * BM * (BK + 8);
    __nv_bfloat16* BsH = AsL + 2 * BM * (BK + 8);  // [2][32][136]
    __nv_bfloat16* BsL = BsH + 2 * BK * (BN + 8);

    const float* b0 = B0 + (size_t)n * sB0;
    const float* b1 = B1 + (size_t)n * sB1;

    // loader geometry
    const int aRow  = tid >> 1;           // 0..127
    const int aCol  = (tid & 1) * 16;     // 0 / 16
    const int bRow  = tid >> 3;           // 0..31
    const int bColF = (tid & 7) * 16;     // 0..112 (fp32 columns)

    const __nv_bfloat16* aGh = A2 + (size_t)(m0 + aRow) * K + aCol;
    const __nv_bfloat16* aGl = aGh + (size_t)BM * nMB * K;   // lo block offset = M*K
    const int sOff = s0 + bColF;

    float acc[4][4][4];
    #pragma unroll
    for (int mi = 0; mi < 4; mi++)
        #pragma unroll
        for (int ni = 0; ni < 4; ni++)
            #pragma unroll
            for (int q = 0; q < 4; q++) acc[mi][ni][q] = 0.f;

    u32 ahBase = (u32)__cvta_generic_to_shared(AsH);
    u32 alBase = (u32)__cvta_generic_to_shared(AsL);
    u32 bhBase = (u32)__cvta_generic_to_shared(BsH);
    u32 blBase = (u32)__cvta_generic_to_shared(BsL);
    const u32 aBuf = BM * (BK + 8) * 2;
    const u32 bBuf = BK * (BN + 8) * 2;
    const u32 aOff = ((wm * 64 + (lane & 15)) * (BK + 8) + ((lane >> 4) << 3)) * 2;
    const u32 bOff = ((lane & 15) * (BN + 8) + wn * 32 + ((lane >> 4) << 3)) * 2;
    const u32 A_MI = 16 * (BK + 8) * 2;
    const u32 B_KS = 16 * (BN + 8) * 2;

    const int nT = K / BK;
    uint4 pah0, pah1, pal0, pal1;
    float4 pb[4];

    // prefetch tile 0
    {
        pah0 = *(const uint4*)aGh;
        pah1 = *(const uint4*)(aGh + 8);
        pal0 = *(const uint4*)aGl;
        pal1 = *(const uint4*)(aGl + 8);
        int r = bRow;
        const float* rp = (r < Ksplit) ? b0 + (size_t)r * HWD
                                       : b1 + (size_t)(r - Ksplit) * HWD;
        rp += sOff;
        pb[0] = *(const float4*)rp;
        pb[1] = *(const float4*)(rp + 4);
        pb[2] = *(const float4*)(rp + 8);
        pb[3] = *(const float4*)(rp + 12);
    }

    for (int t = 0; t < nT; t++) {
        const int buf = t & 1;
        // stage A
        *(uint4*)&AsH[buf * BM * (BK + 8) + aRow * (BK + 8) + aCol]     = pah0;
        *(uint4*)&AsH[buf * BM * (BK + 8) + aRow * (BK + 8) + aCol + 8] = pah1;
        *(uint4*)&AsL[buf * BM * (BK + 8) + aRow * (BK + 8) + aCol]     = pal0;
        *(uint4*)&AsL[buf * BM * (BK + 8) + aRow * (BK + 8) + aCol + 8] = pal1;
        // split + stage B
        {
            U16B hh, ll;
            const float* pf = (const float*)pb;
            #pragma unroll
            for (int j = 0; j < 16; j++) {
                __nv_bfloat16 h, l;
                split_bf16(pf[j], h, l);
                hh.v[j] = h; ll.v[j] = l;
            }
            __nv_bfloat16* dh = &BsH[buf * BK * (BN + 8) + bRow * (BN + 8) + bColF];
            __nv_bfloat16* dl = &BsL[buf * BK * (BN + 8) + bRow * (BN + 8) + bColF];
            *(uint4*)dh = hh.q[0];
            *(uint4*)(dh + 8) = hh.q[1];
            *(uint4*)dl = ll.q[0];
            *(uint4*)(dl + 8) = ll.q[1];
        }
        __syncthreads();

        if (t + 1 < nT) {
            const __nv_bfloat16* agh = aGh + (size_t)(t + 1) * BK;
            const __nv_bfloat16* agl = aGl + (size_t)(t + 1) * BK;
            pah0 = *(const uint4*)agh;
            pah1 = *(const uint4*)(agh + 8);
            pal0 = *(const uint4*)agl;
            pal1 = *(const uint4*)(agl + 8);
            int r = (t + 1) * BK + bRow;
            const float* rp = (r < Ksplit) ? b0 + (size_t)r * HWD
                                           : b1 + (size_t)(r - Ksplit) * HWD;
            rp += sOff;
            pb[0] = *(const float4*)rp;
            pb[1] = *(const float4*)(rp + 4);
            pb[2] = *(const float4*)(rp + 8);
            pb[3] = *(const float4*)(rp + 12);
        }

        const u32 ahA = ahBase + aOff + buf * aBuf;
        const u32 alA = alBase + aOff + buf * aBuf;
        const u32 bhA = bhBase + bOff + buf * bBuf;
        const u32 blA = blBase + bOff + buf * bBuf;

        #pragma unroll
        for (int ks = 0; ks < 2; ks++) {
            u32 rbh0[4], rbh1[4], rbl0[4], rbl1[4];
            ldsm4t(rbh0, bhA + ks * B_KS);
            ldsm4t(rbh1, bhA + ks * B_KS + 32);
            ldsm4t(rbl0, blA + ks * B_KS);
            ldsm4t(rbl1, blA + ks * B_KS + 32);

            u32 ra[4][4];
            // Ah pass: Ah*Bh + Ah*Bl
            #pragma unroll
            for (int mi = 0; mi < 4; mi++) ldsm4(ra[mi], ahA + mi * A_MI + ks * 32);
            #pragma unroll
            for (int mi = 0; mi < 4; mi++) {
                mma16816(acc[mi][0], ra[mi], &rbh0[0]);
                mma16816(acc[mi][1], ra[mi], &rbh0[2]);
                mma16816(acc[mi][2], ra[mi], &rbh1[0]);
                mma16816(acc[mi][3], ra[mi], &rbh1[2]);
            }
            #pragma unroll
            for (int mi = 0; mi < 4; mi++) {
                mma16816(acc[mi][0], ra[mi], &rbl0[0]);
                mma16816(acc[mi][1], ra[mi], &rbl0[2]);
                mma16816(acc[mi][2], ra[mi], &rbl1[0]);
                mma16816(acc[mi][3], ra[mi], &rbl1[2]);
            }
            // Al pass: Al*Bh
            #pragma unroll
            for (int mi = 0; mi < 4; mi++) ldsm4(ra[mi], alA + mi * A_MI + ks * 32);
            #pragma unroll
            for (int mi = 0; mi < 4; mi++) {
                mma16816(acc[mi][0], ra[mi], &rbh0[0]);
                mma16816(acc[mi][1], ra[mi], &rbh0[2]);
                mma16816(acc[mi][2], ra[mi], &rbh1[0]);
                mma16816(acc[mi][3], ra[mi], &rbh1[2]);
            }
        }
        __syncthreads();
    }

    // epilogue (fp32)
    const int orow = lane >> 2;
    const int scol = (lane & 3) * 2;
    float* y = Y + (size_t)n * sY;
    #pragma unroll
    for (int mi = 0; mi < 4; mi++) {
        const int oA = m0 + wm * 64 + mi * 16 + orow;
        const int oB = oA + 8;
        const float biA = bias[oA], scA = scale[oA], taA = tadd[oA];
        const float biB = bias[oB], scB = scale[oB], taB = tadd[oB];
        #pragma unroll
        for (int ni = 0; ni < 4; ni++) {
            const int s = s0 + wn * 32 + ni * 8 + scol;
            float2 r0 = make_float2(
                fmaxf((acc[mi][ni][0] + biA) * scA + taA, 0.f),
                fmaxf((acc[mi][ni][1] + biA) * scA + taA, 0.f));
            float2 r1 = make_float2(
                fmaxf((acc[mi][ni][2] + biB) * scB + taB, 0.f),
                fmaxf((acc[mi][ni][3] + biB) * scB + taB, 0.f));
            *(float2*)(y + (size_t)oA * HWD + s) = r0;
            *(float2*)(y + (size_t)oB * HWD + s) = r1;
        }
    }
}

// ==================== 19-way attention ====================
__global__ __launch_bounds__(256) void attn_k() {
    const int n = blockIdx.y;
    __shared__ __align__(8) float kk_s[KC * 20];
    __shared__ __align__(8) float val_s[KC * 20];
    for (int idx = threadIdx.x; idx < KC * 20; idx += 256) {
        kk_s[idx]  = g_kk[(size_t)n * KC * 20 + idx];
        val_s[idx] = g_val[(size_t)n * KC * 20 + idx];
    }
    __syncthreads();

    const int sa = blockIdx.x * 512 + threadIdx.x;
    const float* qn = g_q2 + (size_t)n * KC * HWD;

    u64 lgA[10], lgB[10];
    #pragma unroll
    for (int t = 0; t < 10; t++) { lgA[t] = 0ull; lgB[t] = 0ull; }

    #pragma unroll 2
    for (int c = 0; c < KC; c++) {
        float qa = qn[(size_t)c * HWD + sa];
        float qb = qn[(size_t)c * HWD + sa + 256];
        u64 qa2 = pk2(qa, qa), qb2 = pk2(qb, qb);
        const u64* kr = (const u64*)&kk_s[c * 20];
        #pragma unroll
        for (int t = 0; t < 10; t++) {
            u64 kv = kr[t];
            ffma2(lgA[t], qa2, kv);
            ffma2(lgB[t], qb2, kv);
        }
    }

    float la[20], lb[20];
    #pragma unroll
    for (int t = 0; t < 10; t++) {
        float2 va = upk(lgA[t]); la[2 * t] = va.x; la[2 * t + 1] = va.y;
        float2 vb = upk(lgB[t]); lb[2 * t] = vb.x; lb[2 * t + 1] = vb.y;
    }
    const float scl = 0.0625f;
    float mA = -3.4e38f, mB = -3.4e38f;
    #pragma unroll
    for (int k = 0; k < KCL; k++) {
        la[k] *= scl; lb[k] *= scl;
        mA = fmaxf(mA, la[k]); mB = fmaxf(mB, lb[k]);
    }
    float sA = 0.f, sB = 0.f;
    #pragma unroll
    for (int k = 0; k < KCL; k++) {
        la[k] = __expf(la[k] - mA); sA += la[k];
        lb[k] = __expf(lb[k] - mB); sB += lb[k];
    }
    const float ivA = 1.f / sA, ivB = 1.f / sB;
    #pragma unroll
    for (int k = 0; k < KCL; k++) { la[k] *= ivA; lb[k] *= ivB; }
    la[19] = 0.f; lb[19] = 0.f;

    u64 sA2[10], sB2[10];
    #pragma unroll
    for (int t = 0; t < 10; t++) {
        sA2[t] = pk2(la[2 * t], la[2 * t + 1]);
        sB2[t] = pk2(lb[2 * t], lb[2 * t + 1]);
    }

    float* cn = g_ctx + (size_t)n * KC * HWD;
    #pragma unroll 2
    for (int c = 0; c < KC; c++) {
        const u64* vr = (const u64*)&val_s[c * 20];
        u64 aA = 0ull, aB = 0ull;
        #pragma unroll
        for (int t = 0; t < 10; t++) {
            u64 vv = vr[t];
            ffma2(aA, sA2[t], vv);
            ffma2(aB, sB2[t], vv);
        }
        float2 va = upk(aA), vb = upk(aB);
        cn[(size_t)c * HWD + sa] = va.x + va.y;
        cn[(size_t)c * HWD + sa + 256] = vb.x + vb.y;
    }
}

// ==================== host driver ====================
extern "C" void kernel_launch(void* const* d_in, const int* in_sizes, int n_in,
                              void* d_out, int out_size) {
    const float* feats = (const float*)d_in[0];
    const float* probs = (const float*)d_in[1];
    const float* wp1 = (const float*)d_in[2];
    const float* bp1 = (const float*)d_in[3];
    const float* sp1 = (const float*)d_in[4];
    const float* tp1 = (const float*)d_in[5];
    const float* wp2 = (const float*)d_in[6];
    const float* bp2 = (const float*)d_in[7];
    const float* sp2 = (const float*)d_in[8];
    const float* tp2 = (const float*)d_in[9];
    const float* wo1 = (const float*)d_in[10];
    const float* bo1 = (const float*)d_in[11];
    const float* so1 = (const float*)d_in[12];
    const float* to1 = (const float*)d_in[13];
    const float* wo2 = (const float*)d_in[14];
    const float* bo2 = (const float*)d_in[15];
    const float* so2 = (const float*)d_in[16];
    const float* to2 = (const float*)d_in[17];
    const float* wd  = (const float*)d_in[18];
    const float* bd  = (const float*)d_in[19];
    const float* sd  = (const float*)d_in[20];
    const float* td  = (const float*)d_in[21];
    const float* wu  = (const float*)d_in[22];
    const float* bu  = (const float*)d_in[23];
    const float* su  = (const float*)d_in[24];
    const float* tu  = (const float*)d_in[25];
    const float* wf  = (const float*)d_in[26];
    const float* bf  = (const float*)d_in[27];
    const float* sf  = (const float*)d_in[28];
    const float* tf  = (const float*)d_in[29];
    float* out = (float*)d_out;

    void *pproxy, *pt1, *pkk, *pval, *pq1, *pq2, *pctx, *pup;
    void *pw1, *pw2, *pwu, *pwf;
    cudaGetSymbolAddress(&pproxy, g_proxy);
    cudaGetSymbolAddress(&pt1, g_t1);
    cudaGetSymbolAddress(&pkk, g_kk);
    cudaGetSymbolAddress(&pval, g_val);
    cudaGetSymbolAddress(&pq1, g_q1);
    cudaGetSymbolAddress(&pq2, g_q2);
    cudaGetSymbolAddress(&pctx, g_ctx);
    cudaGetSymbolAddress(&pup, g_up);
    cudaGetSymbolAddress(&pw1, g_wp1_2);
    cudaGetSymbolAddress(&pw2, g_wp2_2);
    cudaGetSymbolAddress(&pwu, g_wu_2);
    cudaGetSymbolAddress(&pwf, g_wf_2);

    const int SMEM_GEMM = (2 * BM * (BK + 8) * 2 + 2 * BK * (BN + 8) * 2) * 2; // 75776 B
    cudaFuncSetAttribute(gemm_mma_cbr, cudaFuncAttributeMaxDynamicSharedMemorySize, SMEM_GEMM);

    // weight splits
    conv_w<<<(KC * CIN + 255) / 256, 256>>>(wp1, (__nv_bfloat16*)pw1, KC * CIN);
    conv_w<<<(KC * KC + 255) / 256, 256>>>(wp2, (__nv_bfloat16*)pw2, KC * KC);
    conv_w<<<(CIN * KC + 255) / 256, 256>>>(wu, (__nv_bfloat16*)pwu, CIN * KC);
    conv_w<<<(OUTC * 2 * CIN + 255) / 256, 256>>>(wf, (__nv_bfloat16*)pwf, OUTC * 2 * CIN);

    // softmax + proxy + object branch
    softmax_k<<<NB * KCL, 256>>>(probs);
    proxy_k<<<dim3(32, NB), 256>>>(feats);
    obj_gemm<<<dim3(16, NB), 256, CIN * 22 * 4>>>(wo1, bo1, so1, to1,
        (const float*)pproxy, (float*)pt1, CIN);
    obj_gemm<<<dim3(16, NB), 256, CIN * 22 * 4>>>(wd, bd, sd, td,
        (const float*)pproxy, (float*)pval, CIN);
    obj_gemm<<<dim3(16, NB), 256, KC * 22 * 4>>>(wo2, bo2, so2, to2,
        (const float*)pt1, (float*)pkk, KC);

    // f_pixel stage 1: q1 = cbr(wp1 @ feats)     M=256, K=512
    gemm_mma_cbr<<<dim3((HWD / BN) * (KC / BM), 1, NB), 256, SMEM_GEMM>>>(
        (const __nv_bfloat16*)pw1, CIN, KC / BM,
        feats, feats, CIN, bp1, sp1, tp1,
        (float*)pq1, (long)CIN * HWD, (long)CIN * HWD, (long)KC * HWD);

    // f_pixel stage 2: q2 = cbr(wp2 @ q1)        M=256, K=256
    gemm_mma_cbr<<<dim3((HWD / BN) * (KC / BM), 1, NB), 256, SMEM_GEMM>>>(
        (const __nv_bfloat16*)pw2, KC, KC / BM,
        (const float*)pq1, (const float*)pq1, KC, bp2, sp2, tp2,
        (float*)pq2, (long)KC * HWD, (long)KC * HWD, (long)KC * HWD);

    // attention -> ctx
    attn_k<<<dim3(HWD / 512, NB), 256>>>();

    // f_up: up = cbr(wu @ ctx)                   M=512, K=256
    gemm_mma_cbr<<<dim3((HWD / BN) * (CIN / BM), 1, NB), 256, SMEM_GEMM>>>(
        (const __nv_bfloat16*)pwu, KC, CIN / BM,
        (const float*)pctx, (const float*)pctx, KC, bu, su, tu,
        (float*)pup, (long)KC * HWD, (long)KC * HWD, (long)CIN * HWD);

    // final: out = cbr(wf @ cat[up, feats])      M=512, K=1024, Ksplit=512
    gemm_mma_cbr<<<dim3((HWD / BN) * (OUTC / BM), 1, NB), 256, SMEM_GEMM>>>(
        (const __nv_bfloat16*)pwf, 2 * CIN, OUTC / BM,
        (const float*)pup, feats, CIN, bf, sf, tf,
        out, (long)CIN * HWD, (long)CIN * HWD, (long)OUTC * HWD);
}